// round 11
// baseline (speedup 1.0000x reference)
#include <cuda_runtime.h>
#include <cuda_bf16.h>
#include <cuda_fp16.h>
#include <stdint.h>

#define N_NODES 100000
#define N_EDGES 1600000
#define DDIM    128
#define CAP     96

// Padded bf16 tile: rows x 128 cols, row stride 272 bytes (136 bf16)
#define TROW   272
#define TBYTES (128 * TROW)   // 34816 (full 128-row tile)
#define HTB    (64 * TROW)    // 17408 (64-row tile)

// B streaming piece: 128 n-rows x 32 K-cols bf16, 80B padded rows (bank-perfect)
#define PROW   80
#define PPB    (128 * PROW)   // 10240 per hi or lo half
#define PIECE  (2 * PPB)      // 20480 (hi | lo)

// Allocation-free scratch
__device__ __half g_proj[(size_t)N_NODES * DDIM];
__device__ float  g_neigh[(size_t)N_NODES * DDIM];
__device__ int2   g_bucket[(size_t)N_NODES * CAP];
__device__ int    g_cnt[N_NODES];
// Precomputed bf16 hi/lo weight tiles (16B-aligned for cp.async)
__device__ __align__(16) char g_w1t[2 * TBYTES];      // hi | lo
__device__ __align__(16) char g_w2t[2][2 * TBYTES];   // per K-chunk: hi | lo

// ===========================================================================
// PTX helpers (sm_80-compatible: safe for plain sm_103 ptxas target)
// ===========================================================================
__device__ __forceinline__ uint32_t smem_u32(const void* p) {
    uint32_t a;
    asm("{ .reg .u64 t; cvta.to.shared.u64 t, %1; cvt.u32.u64 %0, t; }"
        : "=r"(a) : "l"(p));
    return a;
}

__device__ __forceinline__ void cpa16(uint32_t saddr, const void* g) {
    asm volatile("cp.async.cg.shared.global [%0], [%1], 16;"
                 :: "r"(saddr), "l"(g) : "memory");
}
#define CP_COMMIT()  asm volatile("cp.async.commit_group;" ::: "memory")
#define CP_WAIT_N(n) asm volatile("cp.async.wait_group %0;" :: "n"(n) : "memory")

__device__ __forceinline__ void ldsm_x4(uint32_t* r, uint32_t addr) {
    asm volatile("ldmatrix.sync.aligned.m8n8.x4.shared.b16 {%0,%1,%2,%3}, [%4];"
                 : "=r"(r[0]), "=r"(r[1]), "=r"(r[2]), "=r"(r[3]) : "r"(addr));
}

__device__ __forceinline__ void mma16816(float* c, const uint32_t* a,
                                         uint32_t b0, uint32_t b1) {
    asm volatile(
        "mma.sync.aligned.m16n8k16.row.col.f32.bf16.bf16.f32 "
        "{%0,%1,%2,%3}, {%4,%5,%6,%7}, {%8,%9}, {%0,%1,%2,%3};"
        : "+f"(c[0]), "+f"(c[1]), "+f"(c[2]), "+f"(c[3])
        : "r"(a[0]), "r"(a[1]), "r"(a[2]), "r"(a[3]), "r"(b0), "r"(b1));
}

// ldmatrix lane address in a TROW-padded A tile
__device__ __forceinline__ uint32_t ldsm_addr(uint32_t base, int r0, int k0) {
    int lane = threadIdx.x & 31;
    int mat = lane >> 3, rim = lane & 7;
    int row = r0 + ((mat & 1) << 3) + rim;
    int kc  = k0 + ((mat >> 1) << 3);
    return base + (uint32_t)(row * TROW + kc * 2);
}
// ldmatrix lane address in a PROW-padded B piece (k local to the piece, 0..31)
__device__ __forceinline__ uint32_t ldsm_addr_p(uint32_t base, int n0, int kl) {
    int lane = threadIdx.x & 31;
    int mat = lane >> 3, rim = lane & 7;
    int row = n0 + ((mat & 1) << 3) + rim;
    int kc  = kl + ((mat >> 1) << 3);
    return base + (uint32_t)(row * PROW + kc * 2);
}

// fp32x4 -> bf16 hi/lo split packed as 2x uint2
__device__ __forceinline__ void cvt4(float4 v, uint2& hi, uint2& lo) {
    __nv_bfloat162 h01 = __float22bfloat162_rn(make_float2(v.x, v.y));
    __nv_bfloat162 h23 = __float22bfloat162_rn(make_float2(v.z, v.w));
    float2 f01 = __bfloat1622float2(h01);
    float2 f23 = __bfloat1622float2(h23);
    __nv_bfloat162 l01 = __float22bfloat162_rn(make_float2(v.x - f01.x, v.y - f01.y));
    __nv_bfloat162 l23 = __float22bfloat162_rn(make_float2(v.z - f23.x, v.w - f23.y));
    hi.x = *reinterpret_cast<uint32_t*>(&h01);
    hi.y = *reinterpret_cast<uint32_t*>(&h23);
    lo.x = *reinterpret_cast<uint32_t*>(&l01);
    lo.y = *reinterpret_cast<uint32_t*>(&l23);
}

// Issue async copy of B piece p (32 K-cols) from a TROW tile into a piece buffer.
// 1024 x 16B chunks: [hi/lo][128 rows][4 x 16B].
__device__ __forceinline__ void issue_piece(uint32_t dst, const char* tile, int p,
                                            int tid) {
    #pragma unroll
    for (int v = 0; v < 4; v++) {
        int i = tid + v * 256;              // 0..1023
        int h = i >> 9, rem = i & 511;
        int j = rem >> 2, cc = rem & 3;
        cpa16(dst + (uint32_t)(h * PPB + j * PROW + cc * 16),
              tile + (size_t)h * TBYTES + (size_t)j * TROW + p * 64 + cc * 16);
    }
    CP_COMMIT();
}

// One quarter (2 k-steps = 32 K-cols): 3-term bf16 MMA.
// A from TROW tile at global k = kA + {0,16}; B from piece buffer (local k).
__device__ __forceinline__ void mma_quarter(
    float (&c)[2][4][4], uint32_t ahi, uint32_t alo, uint32_t pbuf,
    int m_base, int n_base, int kA) {
    #pragma unroll
    for (int half = 0; half < 2; half++) {
        int kl = half * 16;
        uint32_t ah[2][4], al[2][4];
        #pragma unroll
        for (int mt = 0; mt < 2; mt++) {
            ldsm_x4(ah[mt], ldsm_addr(ahi, m_base + 16 * mt, kA + kl));
            ldsm_x4(al[mt], ldsm_addr(alo, m_base + 16 * mt, kA + kl));
        }
        uint32_t bh[4][2], bl[4][2];
        #pragma unroll
        for (int ng = 0; ng < 2; ng++) {
            uint32_t t[4];
            ldsm_x4(t, ldsm_addr_p(pbuf, n_base + ng * 16, kl));
            bh[ng * 2 + 0][0] = t[0]; bh[ng * 2 + 0][1] = t[2];
            bh[ng * 2 + 1][0] = t[1]; bh[ng * 2 + 1][1] = t[3];
            ldsm_x4(t, ldsm_addr_p(pbuf + PPB, n_base + ng * 16, kl));
            bl[ng * 2 + 0][0] = t[0]; bl[ng * 2 + 0][1] = t[2];
            bl[ng * 2 + 1][0] = t[1]; bl[ng * 2 + 1][1] = t[3];
        }
        #pragma unroll
        for (int mt = 0; mt < 2; mt++)
            #pragma unroll
            for (int nt = 0; nt < 4; nt++) {
                mma16816(c[mt][nt], ah[mt], bh[nt][0], bh[nt][1]);
                mma16816(c[mt][nt], ah[mt], bl[nt][0], bl[nt][1]);
                mma16816(c[mt][nt], al[mt], bh[nt][0], bh[nt][1]);
            }
    }
}

// ===========================================================================
// Weight precompute: W1/W2 -> bf16 hi/lo padded tiles (once per launch)
// ===========================================================================
__global__ __launch_bounds__(256) void prep_w_kernel(
    const float* __restrict__ W1, const float* __restrict__ W2) {
    int idx = blockIdx.x * 256 + threadIdx.x;     // 0..12287
    int set = idx >> 12;                          // 0:W1  1:W2c0  2:W2c1
    int i = idx & 4095;
    int r = i >> 5, kg = i & 31;
    const float* src;
    char* dst;
    if (set == 0) { src = &W1[(size_t)r * 128];                   dst = g_w1t; }
    else          { src = &W2[(size_t)r * 256 + (set - 1) * 128]; dst = g_w2t[set - 1]; }
    float4 w = ((const float4*)src)[kg];
    uint2 hi, lo; cvt4(w, hi, lo);
    uint32_t off = (uint32_t)(r * TROW + kg * 8);
    *(uint2*)(dst + off)          = hi;
    *(uint2*)(dst + TBYTES + off) = lo;
}

// ===========================================================================
// Graph-side kernels (unchanged)
// ===========================================================================
__global__ void zero_cnt_kernel() {
    int i = blockIdx.x * blockDim.x + threadIdx.x;
    if (i < N_NODES) g_cnt[i] = 0;
}

__global__ __launch_bounds__(256) void fill_kernel(
    const int* __restrict__ erow, const int* __restrict__ ecol,
    const float* __restrict__ eval_) {
    int e = blockIdx.x * blockDim.x + threadIdx.x;
    if (e >= N_EDGES) return;
    int r = erow[e];
    int slot = atomicAdd(&g_cnt[r], 1);
    if (slot < CAP) {
        g_bucket[(size_t)r * CAP + slot] = make_int2(ecol[e], __float_as_int(eval_[e]));
    }
}

__global__ __launch_bounds__(256) void gather_kernel() {
    int node = (blockIdx.x * blockDim.x + threadIdx.x) >> 5;
    if (node >= N_NODES) return;
    int lane = threadIdx.x & 31;
    int sub = lane >> 4;
    int q   = lane & 15;

    int n = g_cnt[node]; if (n > CAP) n = CAP;
    const int2* bkt = &g_bucket[(size_t)node * CAP];
    float acc[8] = {};

    #define PAIR(E) {                                                        \
        int2 cv = __ldg(&bkt[(E) + sub]);                                    \
        float v = __int_as_float(cv.y);                                      \
        uint4 u = *(const uint4*)&g_proj[(size_t)cv.x * DDIM + q * 8];       \
        float2 f0 = __half22float2(*reinterpret_cast<__half2*>(&u.x));       \
        float2 f1 = __half22float2(*reinterpret_cast<__half2*>(&u.y));       \
        float2 f2 = __half22float2(*reinterpret_cast<__half2*>(&u.z));       \
        float2 f3 = __half22float2(*reinterpret_cast<__half2*>(&u.w));       \
        acc[0] += v * f0.x; acc[1] += v * f0.y;                              \
        acc[2] += v * f1.x; acc[3] += v * f1.y;                              \
        acc[4] += v * f2.x; acc[5] += v * f2.y;                              \
        acc[6] += v * f3.x; acc[7] += v * f3.y; }

    int e = 0;
    for (; e + 8 <= n; e += 8) { PAIR(e) PAIR(e + 2) PAIR(e + 4) PAIR(e + 6) }
    for (; e + 2 <= n; e += 2) { PAIR(e) }
    if (e < n && sub == 0) {
        int2 cv = __ldg(&bkt[e]);
        float v = __int_as_float(cv.y);
        uint4 u = *(const uint4*)&g_proj[(size_t)cv.x * DDIM + q * 8];
        float2 f0 = __half22float2(*reinterpret_cast<__half2*>(&u.x));
        float2 f1 = __half22float2(*reinterpret_cast<__half2*>(&u.y));
        float2 f2 = __half22float2(*reinterpret_cast<__half2*>(&u.z));
        float2 f3 = __half22float2(*reinterpret_cast<__half2*>(&u.w));
        acc[0] += v * f0.x; acc[1] += v * f0.y;
        acc[2] += v * f1.x; acc[3] += v * f1.y;
        acc[4] += v * f2.x; acc[5] += v * f2.y;
        acc[6] += v * f3.x; acc[7] += v * f3.y;
    }
    #undef PAIR

    #pragma unroll
    for (int k = 0; k < 8; k++)
        acc[k] += __shfl_xor_sync(~0u, acc[k], 16);

    if (sub == 0) {
        float4* dst = (float4*)&g_neigh[(size_t)node * DDIM + q * 8];
        dst[0] = make_float4(acc[0], acc[1], acc[2], acc[3]);
        dst[1] = make_float4(acc[4], acc[5], acc[6], acc[7]);
    }
}

// ===========================================================================
// GEMM1 (HMMA): g_proj[64-tile,128] = fp16( x @ W1^T ), B streamed in pieces
// smem: Ahi|Alo (2x17408) + 2 piece buffers (2x20480) = 75776 -> 3 blocks/SM
// ===========================================================================
#define G1_SMEM (2 * HTB + 2 * PIECE)   // 75776

__global__ __launch_bounds__(256, 3)
void gemm1_mma_kernel(const float* __restrict__ input) {
    extern __shared__ char sm[];
    uint32_t AHI = smem_u32(sm);
    uint32_t ALO = AHI + HTB;
    uint32_t B0  = AHI + 2 * HTB;
    uint32_t B1  = B0 + PIECE;

    int tid = threadIdx.x, wid = tid >> 5, lane = tid & 31;
    int row0 = blockIdx.x * 64;

    issue_piece(B0, g_w1t, 0, tid);
    issue_piece(B1, g_w1t, 1, tid);

    // Stage A (64 input rows, hi/lo) while pieces fly
    for (int i = tid; i < 64 * 32; i += 256) {
        int r = i >> 5, kg = i & 31;
        int row = row0 + r; if (row >= N_NODES) row = N_NODES - 1;
        float4 v = ((const float4*)&input[(size_t)row * DDIM])[kg];
        uint2 hi, lo; cvt4(v, hi, lo);
        uint32_t off = (uint32_t)(r * TROW + kg * 8);
        *(uint2*)(sm + off)       = hi;
        *(uint2*)(sm + HTB + off) = lo;
    }
    CP_WAIT_N(1);
    __syncthreads();

    int m_base = (wid & 1) * 32;
    int n_base = (wid >> 1) * 32;
    float c[2][4][4] = {};

    // q0 (piece0 in B0)
    mma_quarter(c, AHI, ALO, B0, m_base, n_base, 0);
    __syncthreads();
    issue_piece(B0, g_w1t, 2, tid);
    CP_WAIT_N(1);
    __syncthreads();
    // q1 (piece1 in B1)
    mma_quarter(c, AHI, ALO, B1, m_base, n_base, 32);
    __syncthreads();
    issue_piece(B1, g_w1t, 3, tid);
    CP_WAIT_N(1);
    __syncthreads();
    // q2 (piece2 in B0)
    mma_quarter(c, AHI, ALO, B0, m_base, n_base, 64);
    CP_WAIT_N(0);
    __syncthreads();
    // q3 (piece3 in B1)
    mma_quarter(c, AHI, ALO, B1, m_base, n_base, 96);

    int qr = lane >> 2, qc = (lane & 3) * 2;
    #pragma unroll
    for (int mt = 0; mt < 2; mt++) {
        int rbase = row0 + m_base + mt * 16 + qr;
        #pragma unroll
        for (int nt = 0; nt < 4; nt++) {
            int col = n_base + nt * 8 + qc;
            if (rbase < N_NODES)
                *(__half2*)&g_proj[(size_t)rbase * DDIM + col] =
                    __floats2half2_rn(c[mt][nt][0], c[mt][nt][1]);
            if (rbase + 8 < N_NODES)
                *(__half2*)&g_proj[(size_t)(rbase + 8) * DDIM + col] =
                    __floats2half2_rn(c[mt][nt][2], c[mt][nt][3]);
        }
    }
}

// ===========================================================================
// GEMM2 (HMMA): out = leaky_relu([in+ne | in*ne] @ W2^T)
// A-sum and A-prod staged ONCE; K=256 as 8 streamed B pieces.
// smem: Ash|Asl|Aph|Apl (4x17408) + 2 piece buffers = 110592 -> 2 blocks/SM
// ===========================================================================
#define G2_SMEM (4 * HTB + 2 * PIECE)   // 110592

__global__ __launch_bounds__(256, 2)
void gemm2_mma_kernel(const float* __restrict__ input, float* __restrict__ out) {
    extern __shared__ char sm[];
    uint32_t ASH = smem_u32(sm);
    uint32_t ASL = ASH + HTB;
    uint32_t APH = ASH + 2 * HTB;
    uint32_t APL = ASH + 3 * HTB;
    uint32_t B0  = ASH + 4 * HTB;
    uint32_t B1  = B0 + PIECE;

    int tid = threadIdx.x, wid = tid >> 5, lane = tid & 31;
    int row0 = blockIdx.x * 64;

    issue_piece(B0, g_w2t[0], 0, tid);
    issue_piece(B1, g_w2t[0], 1, tid);

    // Stage both A tiles (input+neigh read once)
    for (int i = tid; i < 64 * 32; i += 256) {
        int r = i >> 5, kg = i & 31;
        int row = row0 + r; if (row >= N_NODES) row = N_NODES - 1;
        float4 a = ((const float4*)&input[(size_t)row * DDIM])[kg];
        float4 n = ((const float4*)&g_neigh[(size_t)row * DDIM])[kg];
        float4 s = make_float4(a.x + n.x, a.y + n.y, a.z + n.z, a.w + n.w);
        float4 p = make_float4(a.x * n.x, a.y * n.y, a.z * n.z, a.w * n.w);
        uint2 hi, lo;
        uint32_t off = (uint32_t)(r * TROW + kg * 8);
        cvt4(s, hi, lo);
        *(uint2*)(sm + off)           = hi;
        *(uint2*)(sm + HTB + off)     = lo;
        cvt4(p, hi, lo);
        *(uint2*)(sm + 2 * HTB + off) = hi;
        *(uint2*)(sm + 3 * HTB + off) = lo;
    }
    CP_WAIT_N(1);
    __syncthreads();

    int m_base = (wid & 1) * 32;
    int n_base = (wid >> 1) * 32;
    float c[2][4][4] = {};

    #pragma unroll
    for (int qq = 0; qq < 8; qq++) {
        uint32_t ahi = (qq < 4) ? ASH : APH;
        uint32_t alo = (qq < 4) ? ASL : APL;
        uint32_t pbuf = (qq & 1) ? B1 : B0;
        mma_quarter(c, ahi, alo, pbuf, m_base, n_base, (qq & 3) * 32);
        if (qq < 7) {
            __syncthreads();                     // everyone done with this buffer
            if (qq + 2 <= 7)
                issue_piece(pbuf, g_w2t[(qq + 2) >> 2], (qq + 2) & 3, tid);
            if (qq == 6) { CP_WAIT_N(0); } else { CP_WAIT_N(1); }
            __syncthreads();
        }
    }

    int qr = lane >> 2, qc = (lane & 3) * 2;
    #pragma unroll
    for (int mt = 0; mt < 2; mt++) {
        int rbase = row0 + m_base + mt * 16 + qr;
        #pragma unroll
        for (int nt = 0; nt < 4; nt++) {
            int col = n_base + nt * 8 + qc;
            float v0 = c[mt][nt][0], v1 = c[mt][nt][1];
            float v2 = c[mt][nt][2], v3 = c[mt][nt][3];
            v0 = v0 > 0.f ? v0 : 0.01f * v0;
            v1 = v1 > 0.f ? v1 : 0.01f * v1;
            v2 = v2 > 0.f ? v2 : 0.01f * v2;
            v3 = v3 > 0.f ? v3 : 0.01f * v3;
            if (rbase < N_NODES)
                *(float2*)&out[(size_t)rbase * DDIM + col] = make_float2(v0, v1);
            if (rbase + 8 < N_NODES)
                *(float2*)&out[(size_t)(rbase + 8) * DDIM + col] = make_float2(v2, v3);
        }
    }
}

// ===========================================================================
extern "C" void kernel_launch(void* const* d_in, const int* in_sizes, int n_in,
                              void* d_out, int out_size) {
    const float* input = (const float*)d_in[0];
    const int*   erow  = (const int*)d_in[1];
    const int*   ecol  = (const int*)d_in[2];
    const float* eval_ = (const float*)d_in[3];
    const float* W1    = (const float*)d_in[4];
    const float* W2    = (const float*)d_in[5];
    float* out = (float*)d_out;

    cudaFuncSetAttribute(gemm1_mma_kernel, cudaFuncAttributeMaxDynamicSharedMemorySize, G1_SMEM);
    cudaFuncSetAttribute(gemm2_mma_kernel, cudaFuncAttributeMaxDynamicSharedMemorySize, G2_SMEM);

    static cudaStream_t s2 = 0;
    static cudaEvent_t ev1 = 0, ev2 = 0;
    static bool have_fork = false;
    static bool tried = false;
    if (!tried) {
        tried = true;
        if (cudaStreamCreateWithFlags(&s2, cudaStreamNonBlocking) == cudaSuccess &&
            cudaEventCreateWithFlags(&ev1, cudaEventDisableTiming) == cudaSuccess &&
            cudaEventCreateWithFlags(&ev2, cudaEventDisableTiming) == cudaSuccess)
            have_fork = true;
    }

    int g_blocks = (N_NODES + 63) / 64;     // 1563

    if (have_fork) {
        cudaEventRecord(ev1, 0);
        cudaStreamWaitEvent(s2, ev1, 0);
        zero_cnt_kernel<<<(N_NODES + 1023) / 1024, 1024, 0, s2>>>();
        fill_kernel<<<(N_EDGES + 255) / 256, 256, 0, s2>>>(erow, ecol, eval_);
        cudaEventRecord(ev2, s2);
        prep_w_kernel<<<48, 256>>>(W1, W2);
        gemm1_mma_kernel<<<g_blocks, 256, G1_SMEM>>>(input);
        cudaStreamWaitEvent(0, ev2, 0);
    } else {
        zero_cnt_kernel<<<(N_NODES + 1023) / 1024, 1024>>>();
        fill_kernel<<<(N_EDGES + 255) / 256, 256>>>(erow, ecol, eval_);
        prep_w_kernel<<<48, 256>>>(W1, W2);
        gemm1_mma_kernel<<<g_blocks, 256, G1_SMEM>>>(input);
    }

    gather_kernel<<<(N_NODES * 32 + 255) / 256, 256>>>();
    gemm2_mma_kernel<<<g_blocks, 256, G2_SMEM>>>(input, out);
}

// round 12
// speedup vs baseline: 1.3599x; 1.3599x over previous
#include <cuda_runtime.h>
#include <cuda_bf16.h>
#include <cuda_fp16.h>
#include <stdint.h>

#define N_NODES 100000
#define N_EDGES 1600000
#define DDIM    128
#define CAP     96

// Padded fp16 tile: rows x 128 cols, row stride 272 bytes (136 halves)
#define TROW   272
#define TBYTES (128 * TROW)   // 34816 (128-row tile)
#define HTB    (64 * TROW)    // 17408 (64-row tile)

// Allocation-free scratch
__device__ __half g_proj[(size_t)N_NODES * DDIM];
__device__ float  g_neigh[(size_t)N_NODES * DDIM];
__device__ int2   g_bucket[(size_t)N_NODES * CAP];
__device__ int    g_cnt[N_NODES];
// Precomputed fp16 weight tiles (16B-aligned for cp.async)
__device__ __align__(16) char g_w1t[TBYTES];
__device__ __align__(16) char g_w2t[2][TBYTES];   // per K-chunk

// ===========================================================================
// PTX helpers (sm_80-compatible: safe for plain sm_103 ptxas target)
// ===========================================================================
__device__ __forceinline__ uint32_t smem_u32(const void* p) {
    uint32_t a;
    asm("{ .reg .u64 t; cvta.to.shared.u64 t, %1; cvt.u32.u64 %0, t; }"
        : "=r"(a) : "l"(p));
    return a;
}

__device__ __forceinline__ void cpa16(uint32_t saddr, const void* g) {
    asm volatile("cp.async.cg.shared.global [%0], [%1], 16;"
                 :: "r"(saddr), "l"(g) : "memory");
}
#define CP_WAIT() asm volatile("cp.async.commit_group;\n\tcp.async.wait_group 0;" ::: "memory")

__device__ __forceinline__ void ldsm_x4(uint32_t* r, uint32_t addr) {
    asm volatile("ldmatrix.sync.aligned.m8n8.x4.shared.b16 {%0,%1,%2,%3}, [%4];"
                 : "=r"(r[0]), "=r"(r[1]), "=r"(r[2]), "=r"(r[3]) : "r"(addr));
}

// fp16 MMA, fp32 accumulate
__device__ __forceinline__ void mma16816(float* c, const uint32_t* a,
                                         uint32_t b0, uint32_t b1) {
    asm volatile(
        "mma.sync.aligned.m16n8k16.row.col.f32.f16.f16.f32 "
        "{%0,%1,%2,%3}, {%4,%5,%6,%7}, {%8,%9}, {%0,%1,%2,%3};"
        : "+f"(c[0]), "+f"(c[1]), "+f"(c[2]), "+f"(c[3])
        : "r"(a[0]), "r"(a[1]), "r"(a[2]), "r"(a[3]), "r"(b0), "r"(b1));
}

__device__ __forceinline__ uint32_t ldsm_addr(uint32_t base, int r0, int k0) {
    int lane = threadIdx.x & 31;
    int mat = lane >> 3, rim = lane & 7;
    int row = r0 + ((mat & 1) << 3) + rim;
    int kc  = k0 + ((mat >> 1) << 3);
    return base + (uint32_t)(row * TROW + kc * 2);
}

// fp32x4 -> fp16x4 packed as uint2
__device__ __forceinline__ uint2 cvt4h(float4 v) {
    __half2 h01 = __floats2half2_rn(v.x, v.y);
    __half2 h23 = __floats2half2_rn(v.z, v.w);
    uint2 r;
    r.x = *reinterpret_cast<uint32_t*>(&h01);
    r.y = *reinterpret_cast<uint32_t*>(&h23);
    return r;
}

// One K=128 pass, single-term fp16 MMA.
// Warp tile: MT m-tiles of 16 rows, NT n-tiles of 8 cols.
template<int MT, int NT>
__device__ __forceinline__ void mma_k128_t(
    float (&c)[MT][NT][4], uint32_t abase, uint32_t bbase,
    int m_base, int n_base) {
    #pragma unroll
    for (int s = 0; s < 8; s++) {
        int k0 = s * 16;
        uint32_t a[MT][4];
        #pragma unroll
        for (int mt = 0; mt < MT; mt++)
            ldsm_x4(a[mt], ldsm_addr(abase, m_base + 16 * mt, k0));
        uint32_t b[NT][2];
        #pragma unroll
        for (int ng = 0; ng < NT / 2; ng++) {
            uint32_t t[4];
            ldsm_x4(t, ldsm_addr(bbase, n_base + ng * 16, k0));
            b[ng * 2 + 0][0] = t[0]; b[ng * 2 + 0][1] = t[2];
            b[ng * 2 + 1][0] = t[1]; b[ng * 2 + 1][1] = t[3];
        }
        #pragma unroll
        for (int mt = 0; mt < MT; mt++)
            #pragma unroll
            for (int nt = 0; nt < NT; nt++)
                mma16816(c[mt][nt], a[mt], b[nt][0], b[nt][1]);
    }
}

// ===========================================================================
// Weight precompute: W1/W2 -> fp16 padded tiles (once per launch)
// ===========================================================================
__global__ __launch_bounds__(256) void prep_w_kernel(
    const float* __restrict__ W1, const float* __restrict__ W2) {
    int idx = blockIdx.x * 256 + threadIdx.x;     // 0..12287
    int set = idx >> 12;                          // 0:W1  1:W2c0  2:W2c1
    int i = idx & 4095;
    int r = i >> 5, kg = i & 31;
    const float* src;
    char* dst;
    if (set == 0) { src = &W1[(size_t)r * 128];                   dst = g_w1t; }
    else          { src = &W2[(size_t)r * 256 + (set - 1) * 128]; dst = g_w2t[set - 1]; }
    float4 w = ((const float4*)src)[kg];
    *(uint2*)(dst + (uint32_t)(r * TROW + kg * 8)) = cvt4h(w);
}

// ===========================================================================
// Graph-side kernels (unchanged)
// ===========================================================================
__global__ void zero_cnt_kernel() {
    int i = blockIdx.x * blockDim.x + threadIdx.x;
    if (i < N_NODES) g_cnt[i] = 0;
}

__global__ __launch_bounds__(256) void fill_kernel(
    const int* __restrict__ erow, const int* __restrict__ ecol,
    const float* __restrict__ eval_) {
    int e = blockIdx.x * blockDim.x + threadIdx.x;
    if (e >= N_EDGES) return;
    int r = erow[e];
    int slot = atomicAdd(&g_cnt[r], 1);
    if (slot < CAP) {
        g_bucket[(size_t)r * CAP + slot] = make_int2(ecol[e], __float_as_int(eval_[e]));
    }
}

__global__ __launch_bounds__(256) void gather_kernel() {
    int node = (blockIdx.x * blockDim.x + threadIdx.x) >> 5;
    if (node >= N_NODES) return;
    int lane = threadIdx.x & 31;
    int sub = lane >> 4;
    int q   = lane & 15;

    int n = g_cnt[node]; if (n > CAP) n = CAP;
    const int2* bkt = &g_bucket[(size_t)node * CAP];
    float acc[8] = {};

    #define PAIR(E) {                                                        \
        int2 cv = __ldg(&bkt[(E) + sub]);                                    \
        float v = __int_as_float(cv.y);                                      \
        uint4 u = *(const uint4*)&g_proj[(size_t)cv.x * DDIM + q * 8];       \
        float2 f0 = __half22float2(*reinterpret_cast<__half2*>(&u.x));       \
        float2 f1 = __half22float2(*reinterpret_cast<__half2*>(&u.y));       \
        float2 f2 = __half22float2(*reinterpret_cast<__half2*>(&u.z));       \
        float2 f3 = __half22float2(*reinterpret_cast<__half2*>(&u.w));       \
        acc[0] += v * f0.x; acc[1] += v * f0.y;                              \
        acc[2] += v * f1.x; acc[3] += v * f1.y;                              \
        acc[4] += v * f2.x; acc[5] += v * f2.y;                              \
        acc[6] += v * f3.x; acc[7] += v * f3.y; }

    int e = 0;
    for (; e + 8 <= n; e += 8) { PAIR(e) PAIR(e + 2) PAIR(e + 4) PAIR(e + 6) }
    for (; e + 2 <= n; e += 2) { PAIR(e) }
    if (e < n && sub == 0) {
        int2 cv = __ldg(&bkt[e]);
        float v = __int_as_float(cv.y);
        uint4 u = *(const uint4*)&g_proj[(size_t)cv.x * DDIM + q * 8];
        float2 f0 = __half22float2(*reinterpret_cast<__half2*>(&u.x));
        float2 f1 = __half22float2(*reinterpret_cast<__half2*>(&u.y));
        float2 f2 = __half22float2(*reinterpret_cast<__half2*>(&u.z));
        float2 f3 = __half22float2(*reinterpret_cast<__half2*>(&u.w));
        acc[0] += v * f0.x; acc[1] += v * f0.y;
        acc[2] += v * f1.x; acc[3] += v * f1.y;
        acc[4] += v * f2.x; acc[5] += v * f2.y;
        acc[6] += v * f3.x; acc[7] += v * f3.y;
    }
    #undef PAIR

    #pragma unroll
    for (int k = 0; k < 8; k++)
        acc[k] += __shfl_xor_sync(~0u, acc[k], 16);

    if (sub == 0) {
        float4* dst = (float4*)&g_neigh[(size_t)node * DDIM + q * 8];
        dst[0] = make_float4(acc[0], acc[1], acc[2], acc[3]);
        dst[1] = make_float4(acc[4], acc[5], acc[6], acc[7]);
    }
}

// ===========================================================================
// GEMM1 (fp16 HMMA): g_proj[64-tile,128] = fp16( x @ W1^T )
// smem: A (17408) + B (34816) = 52224 -> 4 blocks/SM
// ===========================================================================
#define G1_SMEM (HTB + TBYTES)   // 52224

__global__ __launch_bounds__(256, 4)
void gemm1_mma_kernel(const float* __restrict__ input) {
    extern __shared__ char sm[];
    uint32_t A = smem_u32(sm);
    uint32_t B = A + HTB;

    int tid = threadIdx.x, wid = tid >> 5, lane = tid & 31;
    int row0 = blockIdx.x * 64;

    // Issue B copy (async, 2176 x 16B)
    for (int i = tid; i < TBYTES / 16; i += 256)
        cpa16(B + (uint32_t)i * 16, g_w1t + (size_t)i * 16);

    // Stage A (64 input rows, fp16) while B flies
    for (int i = tid; i < 64 * 32; i += 256) {
        int r = i >> 5, kg = i & 31;
        int row = row0 + r; if (row >= N_NODES) row = N_NODES - 1;
        float4 v = ((const float4*)&input[(size_t)row * DDIM])[kg];
        *(uint2*)(sm + (uint32_t)(r * TROW + kg * 8)) = cvt4h(v);
    }
    CP_WAIT();
    __syncthreads();

    int m_base = (wid & 1) * 32;
    int n_base = (wid >> 1) * 32;
    float c[2][4][4] = {};
    mma_k128_t<2, 4>(c, A, B, m_base, n_base);

    int qr = lane >> 2, qc = (lane & 3) * 2;
    #pragma unroll
    for (int mt = 0; mt < 2; mt++) {
        int rbase = row0 + m_base + mt * 16 + qr;
        #pragma unroll
        for (int nt = 0; nt < 4; nt++) {
            int col = n_base + nt * 8 + qc;
            if (rbase < N_NODES)
                *(__half2*)&g_proj[(size_t)rbase * DDIM + col] =
                    __floats2half2_rn(c[mt][nt][0], c[mt][nt][1]);
            if (rbase + 8 < N_NODES)
                *(__half2*)&g_proj[(size_t)(rbase + 8) * DDIM + col] =
                    __floats2half2_rn(c[mt][nt][2], c[mt][nt][3]);
        }
    }
}

// ===========================================================================
// GEMM2 (fp16 HMMA): out = leaky_relu([in+ne | in*ne] @ W2^T)
// A-sum and A-prod staged ONCE (input+neigh read once); K=256 in registers,
// B restaged per chunk (single buffer + cp.async).
// smem: Asum|Aprod (2x17408) + B (34816) = 69632 -> 3 blocks/SM
// ===========================================================================
#define G2_SMEM (2 * HTB + TBYTES)   // 69632

__global__ __launch_bounds__(256, 3)
void gemm2_mma_kernel(const float* __restrict__ input, float* __restrict__ out) {
    extern __shared__ char sm[];
    uint32_t AS = smem_u32(sm);
    uint32_t AP = AS + HTB;
    uint32_t B  = AS + 2 * HTB;

    int tid = threadIdx.x, wid = tid >> 5, lane = tid & 31;
    int row0 = blockIdx.x * 64;

    // Issue B chunk 0 copy (async)
    for (int i = tid; i < TBYTES / 16; i += 256)
        cpa16(B + (uint32_t)i * 16, g_w2t[0] + (size_t)i * 16);

    // Stage both A tiles (input+neigh read once)
    for (int i = tid; i < 64 * 32; i += 256) {
        int r = i >> 5, kg = i & 31;
        int row = row0 + r; if (row >= N_NODES) row = N_NODES - 1;
        float4 a = ((const float4*)&input[(size_t)row * DDIM])[kg];
        float4 n = ((const float4*)&g_neigh[(size_t)row * DDIM])[kg];
        float4 s = make_float4(a.x + n.x, a.y + n.y, a.z + n.z, a.w + n.w);
        float4 p = make_float4(a.x * n.x, a.y * n.y, a.z * n.z, a.w * n.w);
        uint32_t off = (uint32_t)(r * TROW + kg * 8);
        *(uint2*)(sm + off)       = cvt4h(s);
        *(uint2*)(sm + HTB + off) = cvt4h(p);
    }
    CP_WAIT();
    __syncthreads();

    int m_base = (wid & 1) * 32;
    int n_base = (wid >> 1) * 32;
    float c[2][4][4] = {};

    // Chunk 0: h_sum @ W2[:, 0:128]
    mma_k128_t<2, 4>(c, AS, B, m_base, n_base);
    __syncthreads();

    // Restage B chunk 1, then chunk 1: h_prod @ W2[:, 128:256]
    for (int i = tid; i < TBYTES / 16; i += 256)
        cpa16(B + (uint32_t)i * 16, g_w2t[1] + (size_t)i * 16);
    CP_WAIT();
    __syncthreads();
    mma_k128_t<2, 4>(c, AP, B, m_base, n_base);

    int qr = lane >> 2, qc = (lane & 3) * 2;
    #pragma unroll
    for (int mt = 0; mt < 2; mt++) {
        int rbase = row0 + m_base + mt * 16 + qr;
        #pragma unroll
        for (int nt = 0; nt < 4; nt++) {
            int col = n_base + nt * 8 + qc;
            float v0 = c[mt][nt][0], v1 = c[mt][nt][1];
            float v2 = c[mt][nt][2], v3 = c[mt][nt][3];
            v0 = v0 > 0.f ? v0 : 0.01f * v0;
            v1 = v1 > 0.f ? v1 : 0.01f * v1;
            v2 = v2 > 0.f ? v2 : 0.01f * v2;
            v3 = v3 > 0.f ? v3 : 0.01f * v3;
            if (rbase < N_NODES)
                *(float2*)&out[(size_t)rbase * DDIM + col] = make_float2(v0, v1);
            if (rbase + 8 < N_NODES)
                *(float2*)&out[(size_t)(rbase + 8) * DDIM + col] = make_float2(v2, v3);
        }
    }
}

// ===========================================================================
extern "C" void kernel_launch(void* const* d_in, const int* in_sizes, int n_in,
                              void* d_out, int out_size) {
    const float* input = (const float*)d_in[0];
    const int*   erow  = (const int*)d_in[1];
    const int*   ecol  = (const int*)d_in[2];
    const float* eval_ = (const float*)d_in[3];
    const float* W1    = (const float*)d_in[4];
    const float* W2    = (const float*)d_in[5];
    float* out = (float*)d_out;

    cudaFuncSetAttribute(gemm1_mma_kernel, cudaFuncAttributeMaxDynamicSharedMemorySize, G1_SMEM);
    cudaFuncSetAttribute(gemm2_mma_kernel, cudaFuncAttributeMaxDynamicSharedMemorySize, G2_SMEM);

    static cudaStream_t s2 = 0;
    static cudaEvent_t ev1 = 0, ev2 = 0;
    static bool have_fork = false;
    static bool tried = false;
    if (!tried) {
        tried = true;
        if (cudaStreamCreateWithFlags(&s2, cudaStreamNonBlocking) == cudaSuccess &&
            cudaEventCreateWithFlags(&ev1, cudaEventDisableTiming) == cudaSuccess &&
            cudaEventCreateWithFlags(&ev2, cudaEventDisableTiming) == cudaSuccess)
            have_fork = true;
    }

    int g_blocks = (N_NODES + 63) / 64;     // 1563

    if (have_fork) {
        cudaEventRecord(ev1, 0);
        cudaStreamWaitEvent(s2, ev1, 0);
        zero_cnt_kernel<<<(N_NODES + 1023) / 1024, 1024, 0, s2>>>();
        fill_kernel<<<(N_EDGES + 255) / 256, 256, 0, s2>>>(erow, ecol, eval_);
        cudaEventRecord(ev2, s2);
        prep_w_kernel<<<48, 256>>>(W1, W2);
        gemm1_mma_kernel<<<g_blocks, 256, G1_SMEM>>>(input);
        cudaStreamWaitEvent(0, ev2, 0);
    } else {
        zero_cnt_kernel<<<(N_NODES + 1023) / 1024, 1024>>>();
        fill_kernel<<<(N_EDGES + 255) / 256, 256>>>(erow, ecol, eval_);
        prep_w_kernel<<<48, 256>>>(W1, W2);
        gemm1_mma_kernel<<<g_blocks, 256, G1_SMEM>>>(input);
    }

    gather_kernel<<<(N_NODES * 32 + 255) / 256, 256>>>();
    gemm2_mma_kernel<<<g_blocks, 256, G2_SMEM>>>(input, out);
}